// round 1
// baseline (speedup 1.0000x reference)
#include <cuda_runtime.h>
#include <cuda_bf16.h>
#include <cstdint>

// out[i,j] = rho[i,j] if groups[i]==groups[j] else 0
// d = 11440 (divisible by 4) -> float4 vectorized streaming kernel.

__global__ void __launch_bounds__(256)
pvm_mask_kernel_vec4(const float4* __restrict__ rho,
                     const int*    __restrict__ groups,
                     const int4*   __restrict__ groups4,
                     float4*       __restrict__ out,
                     int d4)
{
    int c4  = blockIdx.x * blockDim.x + threadIdx.x;
    int row = blockIdx.y;
    if (c4 >= d4) return;

    int  gi = __ldg(&groups[row]);
    int4 gj = __ldg(&groups4[c4]);

    size_t idx = (size_t)row * (size_t)d4 + (size_t)c4;
    float4 v = __ldg(&rho[idx]);

    float4 o;
    o.x = (gj.x == gi) ? v.x : 0.0f;
    o.y = (gj.y == gi) ? v.y : 0.0f;
    o.z = (gj.z == gi) ? v.z : 0.0f;
    o.w = (gj.w == gi) ? v.w : 0.0f;

    out[idx] = o;
}

// Scalar fallback in case d % 4 != 0 (not expected for this problem).
__global__ void __launch_bounds__(256)
pvm_mask_kernel_scalar(const float* __restrict__ rho,
                       const int*   __restrict__ groups,
                       float*       __restrict__ out,
                       int d)
{
    int col = blockIdx.x * blockDim.x + threadIdx.x;
    int row = blockIdx.y;
    if (col >= d) return;
    int gi = __ldg(&groups[row]);
    int gj = __ldg(&groups[col]);
    size_t idx = (size_t)row * (size_t)d + (size_t)col;
    out[idx] = (gi == gj) ? __ldg(&rho[idx]) : 0.0f;
}

extern "C" void kernel_launch(void* const* d_in, const int* in_sizes, int n_in,
                              void* d_out, int out_size)
{
    const float* rho    = (const float*)d_in[0];
    const int*   groups = (const int*)d_in[1];
    float*       out    = (float*)d_out;

    int d = in_sizes[1];

    if ((d & 3) == 0) {
        int d4 = d >> 2;
        dim3 block(256);
        dim3 grid((d4 + 255) / 256, d);
        pvm_mask_kernel_vec4<<<grid, block>>>(
            (const float4*)rho, groups, (const int4*)groups, (float4*)out, d4);
    } else {
        dim3 block(256);
        dim3 grid((d + 255) / 256, d);
        pvm_mask_kernel_scalar<<<grid, block>>>(rho, groups, out, d);
    }
}

// round 2
// speedup vs baseline: 1.3861x; 1.3861x over previous
#include <cuda_runtime.h>
#include <cuda_bf16.h>
#include <cstdint>

// out[i,j] = rho[i,j] if groups[i]==groups[j] else 0
//
// groups is sorted into contiguous runs (block-diagonal mask, ~40% nonzero).
// Key optimization: only LOAD rho where the mask can be nonzero. Threads whose
// 4 columns all mismatch the row group store zero WITHOUT reading rho ->
// DRAM read traffic drops ~60% (523MB -> ~209MB). Writes are unavoidable
// (output poisoned). Total ~732MB @ ~6.3TB/s LTS cap.

__global__ void __launch_bounds__(256)
pvm_mask_kernel_vec4(const float4* __restrict__ rho,
                     const int*    __restrict__ groups,
                     const int4*   __restrict__ groups4,
                     float4*       __restrict__ out,
                     int d4)
{
    int c4  = blockIdx.x * blockDim.x + threadIdx.x;
    int row = blockIdx.y;
    if (c4 >= d4) return;

    int  gi = __ldg(&groups[row]);
    int4 gj = __ldg(&groups4[c4]);

    size_t idx = (size_t)row * (size_t)d4 + (size_t)c4;

    bool mx = (gj.x == gi);
    bool my = (gj.y == gi);
    bool mz = (gj.z == gi);
    bool mw = (gj.w == gi);

    float4 o = make_float4(0.0f, 0.0f, 0.0f, 0.0f);

    // Skip the rho load entirely when the whole float4 is masked out.
    // In off-diagonal regions this is uniform across warps/blocks, so the
    // corresponding DRAM lines are never requested.
    if (mx | my | mz | mw) {
        float4 v = rho[idx];
        if (mx) o.x = v.x;
        if (my) o.y = v.y;
        if (mz) o.z = v.z;
        if (mw) o.w = v.w;
    }

    out[idx] = o;
}

// Scalar fallback (d % 4 != 0, not expected here).
__global__ void __launch_bounds__(256)
pvm_mask_kernel_scalar(const float* __restrict__ rho,
                       const int*   __restrict__ groups,
                       float*       __restrict__ out,
                       int d)
{
    int col = blockIdx.x * blockDim.x + threadIdx.x;
    int row = blockIdx.y;
    if (col >= d) return;
    int gi = __ldg(&groups[row]);
    int gj = __ldg(&groups[col]);
    size_t idx = (size_t)row * (size_t)d + (size_t)col;
    float o = 0.0f;
    if (gi == gj) o = rho[idx];
    out[idx] = o;
}

extern "C" void kernel_launch(void* const* d_in, const int* in_sizes, int n_in,
                              void* d_out, int out_size)
{
    const float* rho    = (const float*)d_in[0];
    const int*   groups = (const int*)d_in[1];
    float*       out    = (float*)d_out;

    int d = in_sizes[1];

    if ((d & 3) == 0) {
        int d4 = d >> 2;
        dim3 block(256);
        dim3 grid((d4 + 255) / 256, d);
        pvm_mask_kernel_vec4<<<grid, block>>>(
            (const float4*)rho, groups, (const int4*)groups, (float4*)out, d4);
    } else {
        dim3 block(256);
        dim3 grid((d + 255) / 256, d);
        pvm_mask_kernel_scalar<<<grid, block>>>(rho, groups, out, d);
    }
}

// round 3
// speedup vs baseline: 1.4072x; 1.0153x over previous
#include <cuda_runtime.h>
#include <cuda_bf16.h>
#include <cstdint>

// out[i,j] = rho[i,j] if groups[i]==groups[j] else 0
//
// groups is sorted into contiguous runs -> block-diagonal mask (~40% nonzero).
// Reads of rho are skipped entirely where masked out (saves ~60% read traffic).
// ITEMS=4 float4s per thread for MLP; streaming cache hints (no reuse).

constexpr int ITEMS = 4;
constexpr int TPB   = 256;

__global__ void __launch_bounds__(TPB)
pvm_mask_kernel_vec4x4(const float4* __restrict__ rho,
                       const int*    __restrict__ groups,
                       const int4*   __restrict__ groups4,
                       float4*       __restrict__ out,
                       int d4)
{
    const int row  = blockIdx.y;
    const int gi   = __ldg(&groups[row]);
    const int base = blockIdx.x * (TPB * ITEMS) + threadIdx.x;
    const size_t rowoff = (size_t)row * (size_t)d4;

    int  c4[ITEMS];
    bool ok[ITEMS];
    int4 gj[ITEMS];

    #pragma unroll
    for (int k = 0; k < ITEMS; k++) {
        c4[k] = base + k * TPB;
        ok[k] = (c4[k] < d4);
        if (ok[k]) gj[k] = __ldg(&groups4[c4[k]]);
    }

    #pragma unroll
    for (int k = 0; k < ITEMS; k++) {
        if (!ok[k]) continue;
        bool mx = (gj[k].x == gi);
        bool my = (gj[k].y == gi);
        bool mz = (gj[k].z == gi);
        bool mw = (gj[k].w == gi);

        float4 o = make_float4(0.0f, 0.0f, 0.0f, 0.0f);
        if (mx | my | mz | mw) {
            float4 v = __ldcs(&rho[rowoff + c4[k]]);
            if (mx) o.x = v.x;
            if (my) o.y = v.y;
            if (mz) o.z = v.z;
            if (mw) o.w = v.w;
        }
        __stcs(&out[rowoff + c4[k]], o);
    }
}

// Scalar fallback (d % 4 != 0, not expected here).
__global__ void __launch_bounds__(TPB)
pvm_mask_kernel_scalar(const float* __restrict__ rho,
                       const int*   __restrict__ groups,
                       float*       __restrict__ out,
                       int d)
{
    int col = blockIdx.x * blockDim.x + threadIdx.x;
    int row = blockIdx.y;
    if (col >= d) return;
    int gi = __ldg(&groups[row]);
    int gj = __ldg(&groups[col]);
    size_t idx = (size_t)row * (size_t)d + (size_t)col;
    float o = 0.0f;
    if (gi == gj) o = __ldcs(&rho[idx]);
    __stcs(&out[idx], o);
}

extern "C" void kernel_launch(void* const* d_in, const int* in_sizes, int n_in,
                              void* d_out, int out_size)
{
    const float* rho    = (const float*)d_in[0];
    const int*   groups = (const int*)d_in[1];
    float*       out    = (float*)d_out;

    int d = in_sizes[1];

    if ((d & 3) == 0) {
        int d4 = d >> 2;
        int chunk = TPB * ITEMS;
        dim3 block(TPB);
        dim3 grid((d4 + chunk - 1) / chunk, d);
        pvm_mask_kernel_vec4x4<<<grid, block>>>(
            (const float4*)rho, groups, (const int4*)groups, (float4*)out, d4);
    } else {
        dim3 block(TPB);
        dim3 grid((d + TPB - 1) / TPB, d);
        pvm_mask_kernel_scalar<<<grid, block>>>(rho, groups, out, d);
    }
}